// round 17
// baseline (speedup 1.0000x reference)
#include <cuda_runtime.h>
#include <cuda_fp16.h>
#include <cstdint>

#define E_N 100000
#define T_N 400000
#define MT_N 782               // ceil(E/128)

// Scratch (device globals — no runtime alloc).
__device__ float    g_seg[(long long)E_N * 128];
__device__ float    g_cnt[E_N];
__device__ uint32_t g_fh[(long long)E_N * 64];    // f_edge fp16 [e][k] half2
__device__ uint32_t g_Wb[384 * 64];               // Wb fp16: [n'=j*128+n][k] half2
__device__ uint32_t g_P[(long long)E_N * 192];    // P fp16: [e][384] half2

// ---------------------------------------------------------------------------
// helpers
// ---------------------------------------------------------------------------
__device__ __forceinline__ void mma16(float c[4], const uint32_t a[4],
                                      uint32_t b0, uint32_t b1) {
    asm volatile(
        "mma.sync.aligned.m16n8k16.row.col.f32.f16.f16.f32 "
        "{%0,%1,%2,%3}, {%4,%5,%6,%7}, {%8,%9}, {%0,%1,%2,%3};\n"
        : "+f"(c[0]), "+f"(c[1]), "+f"(c[2]), "+f"(c[3])
        : "r"(a[0]), "r"(a[1]), "r"(a[2]), "r"(a[3]), "r"(b0), "r"(b1));
}

__device__ __forceinline__ void ldm4(uint32_t r[4], uint32_t addr) {
    asm volatile(
        "ldmatrix.sync.aligned.m8n8.x4.shared.b16 {%0,%1,%2,%3}, [%4];"
        : "=r"(r[0]), "=r"(r[1]), "=r"(r[2]), "=r"(r[3]) : "r"(addr));
}

__device__ __forceinline__ void ldm2(uint32_t& r0, uint32_t& r1, uint32_t addr) {
    asm volatile(
        "ldmatrix.sync.aligned.m8n8.x2.shared.b16 {%0,%1}, [%2];"
        : "=r"(r0), "=r"(r1) : "r"(addr));
}

__device__ __forceinline__ void red2(float* p, float x, float y) {
    asm volatile("red.global.add.v2.f32 [%0], {%1,%2};"
                 :: "l"(p), "f"(x), "f"(y) : "memory");
}

__device__ __forceinline__ float gelu_exact(float x) {
    return 0.5f * x * (1.0f + erff(x * 0.70710678118654752f));
}

__device__ __forceinline__ void cpa16(uint32_t dst_smem, const void* src) {
    asm volatile("cp.async.cg.shared.global [%0], [%1], 16;"
                 :: "r"(dst_smem), "l"(src));
}

__device__ __forceinline__ uint32_t pack2h(float lo, float hi) {
    __half2 h = __floats2half2_rn(lo, hi);
    return *reinterpret_cast<uint32_t*>(&h);
}

__device__ __forceinline__ float2 h2f2(uint32_t u) {
    return __half22float2(*reinterpret_cast<__half2*>(&u));
}

// ---------------------------------------------------------------------------
// kernel 0: init — fp16 f_edge, fp16 Wb (Wb[n'][k] = W[j*128+k][n]), zero seg/cnt
// ---------------------------------------------------------------------------
__global__ void init_kernel(const float* __restrict__ fe,
                            const float* __restrict__ W) {
    int i = blockIdx.x * 256 + threadIdx.x;          // 0 .. 3.2M-1
    float4 v = ((const float4*)fe)[i];
    g_fh[2 * i]     = pack2h(v.x, v.y);
    g_fh[2 * i + 1] = pack2h(v.z, v.w);
    ((float4*)g_seg)[i] = make_float4(0.f, 0.f, 0.f, 0.f);
    if (i < 24576) {                                  // 384 n' x 64 k-pairs
        int np = i >> 6, kk = i & 63;
        int j = np >> 7, n = np & 127;
        g_Wb[i] = pack2h(W[(j * 128 + 2 * kk) * 128 + n],
                         W[(j * 128 + 2 * kk + 1) * 128 + n]);
    }
    if (i < E_N) g_cnt[i] = 0.0f;
}

// ---------------------------------------------------------------------------
// kernel A: dense GEMM  P[e][384] = f_edge[e][128] @ Wb^T   (fp16, fp32 acc)
//   BM=128, BN=128, K=128 single-stage. Grid = 782 m-tiles x 3 n-tiles.
// ---------------------------------------------------------------------------
#define ARS 68                               // u32 row stride (272 B)
#define GEMM_SMEM (2 * 128 * ARS * 4)        // 69632 B

__global__ __launch_bounds__(256, 2)
void gemm_kernel() {
    extern __shared__ uint32_t dyn[];
    const int tid   = threadIdx.x;
    const int mt    = blockIdx.x % MT_N;
    const int ntile = blockIdx.x / MT_N;

    const int lane  = tid & 31;
    const int warp  = tid >> 5;
    const int warpM = warp & 3;
    const int warpN = warp >> 2;
    const int gid   = lane >> 2;
    const int t4    = lane & 3;

    const uint32_t dynb = (uint32_t)__cvta_generic_to_shared(dyn);

    // load tiles: A rows e = mt*128+r (clamped), B rows n' = ntile*128+r
#pragma unroll
    for (int s = 0; s < 8; ++s) {
        int fid  = tid + s * 256;
        int r    = fid >> 4;
        int part = (fid & 15) * 4;           // u32 offset within 64-u32 row
        int e    = mt * 128 + r;
        if (e >= E_N) e = E_N - 1;
        cpa16(dynb + (r * ARS + part) * 4, g_fh + (long long)e * 64 + part);
        cpa16(dynb + ((128 + r) * ARS + part) * 4,
              g_Wb + (ntile * 128 + r) * 64 + part);
    }
    asm volatile("cp.async.commit_group;" ::: "memory");
    asm volatile("cp.async.wait_group 0;" ::: "memory");
    __syncthreads();

    const uint32_t aOff = dynb
        + (uint32_t)(warpM * 32 + ((lane >> 3) & 1) * 8 + (lane & 7)) * (ARS * 4)
        + (uint32_t)(lane >> 4) * 16;
    const uint32_t bOff = dynb + (uint32_t)(128 * ARS * 4)
        + (uint32_t)(warpN * 64 + (lane & 7)) * (ARS * 4)
        + (uint32_t)((lane >> 3) & 1) * 16;

    float acc[2][8][4];
#pragma unroll
    for (int a = 0; a < 2; ++a)
#pragma unroll
        for (int b = 0; b < 8; ++b)
#pragma unroll
            for (int c = 0; c < 4; ++c) acc[a][b][c] = 0.0f;

#pragma unroll
    for (int kb = 0; kb < 8; ++kb) {
        const uint32_t k0b = kb * 32;        // 16 halves = 32 B per k-block
        uint32_t a0[4], a1[4];
        ldm4(a0, aOff + k0b);
        ldm4(a1, aOff + k0b + 16 * ARS * 4);
#pragma unroll
        for (int nt = 0; nt < 8; ++nt) {
            uint32_t b0, b1;
            ldm2(b0, b1, bOff + nt * 8 * ARS * 4 + k0b);
            mma16(acc[0][nt], a0, b0, b1);
            mma16(acc[1][nt], a1, b0, b1);
        }
    }

    // store P fp16
#pragma unroll
    for (int mt2 = 0; mt2 < 2; ++mt2) {
        int r0 = warpM * 32 + mt2 * 16 + gid;
        int e0 = mt * 128 + r0;
#pragma unroll
        for (int nt = 0; nt < 8; ++nt) {
            int c0 = warpN * 64 + nt * 8 + t4 * 2;
            long long pcol = ntile * 64 + c0 / 2;
            if (e0 < E_N)
                g_P[(long long)e0 * 192 + pcol] =
                    pack2h(acc[mt2][nt][0], acc[mt2][nt][1]);
            if (e0 + 8 < E_N)
                g_P[(long long)(e0 + 8) * 192 + pcol] =
                    pack2h(acc[mt2][nt][2], acc[mt2][nt][3]);
        }
    }
}

// ---------------------------------------------------------------------------
// kernel B: per-triangle gather P rows, sum, bias+GELU, REDG scatter + count
//   128 triangles/CTA; warp handles 16 (2 per iter via lane halves).
// ---------------------------------------------------------------------------
__global__ __launch_bounds__(256)
void tri_kernel(const float* __restrict__ bias,
                const int* __restrict__ tri) {
    __shared__ int   sIdx[384];
    __shared__ float sBias[128];

    const int tid = threadIdx.x;
    const int t0  = blockIdx.x * 128;        // T = 3125 * 128

    for (int i = tid; i < 384; i += 256) sIdx[i] = tri[(long long)t0 * 3 + i];
    if (tid < 128) sBias[tid] = bias[tid];
    __syncthreads();

    if (tid < 128) atomicAdd(&g_cnt[sIdx[tid * 3 + 2]], 1.0f);

    const int warp = tid >> 5;
    const int lane = tid & 31;
    const int hsel = lane >> 4;              // which of the 2 triangles
    const int lo16 = lane & 15;
    const int off  = lo16 * 4;               // u32 offset in P row (16B step)
    const int c    = lo16 * 8;               // column base (8 floats)

#pragma unroll
    for (int p = 0; p < 8; ++p) {
        const int tt  = warp * 16 + p * 2 + hsel;
        const int i0  = sIdx[tt * 3];
        const int i1  = sIdx[tt * 3 + 1];
        const int dst = sIdx[tt * 3 + 2];

        uint4 v0 = *reinterpret_cast<const uint4*>(g_P + (long long)i0 * 192 + off);
        uint4 v1 = *reinterpret_cast<const uint4*>(g_P + (long long)i1 * 192 + 64 + off);
        uint4 v2 = *reinterpret_cast<const uint4*>(g_P + (long long)dst * 192 + 128 + off);

        float* gp = g_seg + (long long)dst * 128 + c;
        uint32_t u0[4] = {v0.x, v0.y, v0.z, v0.w};
        uint32_t u1[4] = {v1.x, v1.y, v1.z, v1.w};
        uint32_t u2[4] = {v2.x, v2.y, v2.z, v2.w};
#pragma unroll
        for (int q = 0; q < 4; ++q) {
            float2 f0 = h2f2(u0[q]);
            float2 f1 = h2f2(u1[q]);
            float2 f2 = h2f2(u2[q]);
            float sx = f0.x + f1.x + f2.x + sBias[c + 2 * q];
            float sy = f0.y + f1.y + f2.y + sBias[c + 2 * q + 1];
            red2(gp + 2 * q, gelu_exact(sx), gelu_exact(sy));
        }
    }
}

// ---------------------------------------------------------------------------
// kernel 2: segment mean + layernorm. One warp per edge, float4 per lane.
// ---------------------------------------------------------------------------
__global__ __launch_bounds__(256)
void ln_kernel(const float* __restrict__ gamma,
               const float* __restrict__ beta,
               float* __restrict__ out) {
    const int warp = threadIdx.x >> 5;
    const int lane = threadIdx.x & 31;
    const int e = blockIdx.x * 8 + warp;
    if (e >= E_N) return;

    const float inv = 1.0f / fmaxf(g_cnt[e], 1.0f);
    const long long base = (long long)e * 128;

    float4 m = ((const float4*)(g_seg + base))[lane];
    m.x *= inv; m.y *= inv; m.z *= inv; m.w *= inv;

    float s = m.x + m.y + m.z + m.w;
#pragma unroll
    for (int o = 16; o; o >>= 1) s += __shfl_xor_sync(0xffffffffu, s, o);
    const float mu = s * (1.0f / 128.0f);

    float dx = m.x - mu, dy = m.y - mu, dz = m.z - mu, dw = m.w - mu;
    float v = dx * dx + dy * dy + dz * dz + dw * dw;
#pragma unroll
    for (int o = 16; o; o >>= 1) v += __shfl_xor_sync(0xffffffffu, v, o);
    const float rstd = rsqrtf(v * (1.0f / 128.0f) + 1e-5f);

    float4 g = ((const float4*)gamma)[lane];
    float4 bt = ((const float4*)beta)[lane];
    float4 o4;
    o4.x = dx * rstd * g.x + bt.x;
    o4.y = dy * rstd * g.y + bt.y;
    o4.z = dz * rstd * g.z + bt.z;
    o4.w = dw * rstd * g.w + bt.w;
    ((float4*)(out + base))[lane] = o4;
}

// ---------------------------------------------------------------------------
extern "C" void kernel_launch(void* const* d_in, const int* in_sizes, int n_in,
                              void* d_out, int out_size) {
    const float* f_edge = nullptr;
    const float* W      = nullptr;
    const int*   tri    = nullptr;
    const float* vec128[3] = {nullptr, nullptr, nullptr};
    int nv = 0;
    for (int i = 0; i < n_in; ++i) {
        long long sz = in_sizes[i];
        if (sz == (long long)E_N * 128)  f_edge = (const float*)d_in[i];
        else if (sz == 3LL * 128 * 128)  W      = (const float*)d_in[i];
        else if (sz == 3LL * T_N)        tri    = (const int*)d_in[i];
        else if (sz == 128 && nv < 3)    vec128[nv++] = (const float*)d_in[i];
    }
    const float* b     = vec128[0];
    const float* gamma = vec128[1];
    const float* beta  = vec128[2];
    float* out = (float*)d_out;

    cudaFuncSetAttribute(gemm_kernel,
                         cudaFuncAttributeMaxDynamicSharedMemorySize, GEMM_SMEM);

    init_kernel<<<12500, 256>>>(f_edge, W);
    gemm_kernel<<<MT_N * 3, 256, GEMM_SMEM>>>();
    tri_kernel<<<T_N / 128, 256>>>(b, tri);
    ln_kernel<<<E_N / 8, 256>>>(gamma, beta, out);
}